// round 17
// baseline (speedup 1.0000x reference)
#include <cuda_runtime.h>
#include <cuda_bf16.h>
#include <cuda_fp16.h>
#include <cstdint>

#define NMAX 50048
#define EMAX 1000000
#define FD 128     // H*F_OUT == F_IN == 128
#define HH 8       // heads
#define SB 1024    // scan block size
#define TMR 128    // gemm rows per block
#define NTB 8      // n-tiles per block (64 cols; grid.y = 2)
#define SXW 68     // padded sX row stride in words (bank = 4g+t, conflict-free)

// Scratch (static __device__ — no allocations allowed)
__device__ unsigned g_xph[(size_t)NMAX * 64];   // xp as fp16x2 [N][64 words]
__device__ float g_asrc[(size_t)NMAX * HH];
__device__ float g_adst[(size_t)NMAX * HH];
__device__ int   g_cnt[NMAX + 1];
__device__ int   g_rowstart[NMAX + 1];
__device__ int   g_cursor[NMAX];
__device__ int   g_bsum[64];
__device__ int   g_csr[EMAX];
// Pre-packed W fragments for mma.m16n8k16 (kc 0..7, nt 0..15, lane 0..31)
__device__ uint2 g_wbhi[8 * 16 * 32];
__device__ uint2 g_wblo[8 * 16 * 32];

__device__ __forceinline__ void mma16816(float* c, const unsigned* a, uint2 b) {
    asm volatile("mma.sync.aligned.m16n8k16.row.col.f32.bf16.bf16.f32 "
                 "{%0,%1,%2,%3}, {%4,%5,%6,%7}, {%8,%9}, {%0,%1,%2,%3};"
                 : "+f"(c[0]), "+f"(c[1]), "+f"(c[2]), "+f"(c[3])
                 : "r"(a[0]), "r"(a[1]), "r"(a[2]), "r"(a[3]),
                   "r"(b.x), "r"(b.y));
}
__device__ __forceinline__ unsigned bf2_hi(float x, float y, float2& back) {
    __nv_bfloat162 h = __floats2bfloat162_rn(x, y);
    back = __bfloat1622float2(h);
    return *(unsigned*)&h;
}
__device__ __forceinline__ unsigned bf2_pack(float x, float y) {
    __nv_bfloat162 h = __floats2bfloat162_rn(x, y);
    return *(unsigned*)&h;
}
__device__ __forceinline__ unsigned h2_pack(float x, float y) {
    __half2 h = __floats2half2_rn(x, y);
    return *(unsigned*)&h;
}
__device__ __forceinline__ float2 h2_unpack(unsigned u) {
    return __half22float2(*(__half2*)&u);
}
// Accumulate 16 fp16 features (2x uint4) scaled by w into acc[16].
__device__ __forceinline__ void accum16(float* acc, uint4 qa, uint4 qb, float w) {
    float2 f;
    f = h2_unpack(qa.x); acc[0]  = fmaf(w, f.x, acc[0]);  acc[1]  = fmaf(w, f.y, acc[1]);
    f = h2_unpack(qa.y); acc[2]  = fmaf(w, f.x, acc[2]);  acc[3]  = fmaf(w, f.y, acc[3]);
    f = h2_unpack(qa.z); acc[4]  = fmaf(w, f.x, acc[4]);  acc[5]  = fmaf(w, f.y, acc[5]);
    f = h2_unpack(qa.w); acc[6]  = fmaf(w, f.x, acc[6]);  acc[7]  = fmaf(w, f.y, acc[7]);
    f = h2_unpack(qb.x); acc[8]  = fmaf(w, f.x, acc[8]);  acc[9]  = fmaf(w, f.y, acc[9]);
    f = h2_unpack(qb.y); acc[10] = fmaf(w, f.x, acc[10]); acc[11] = fmaf(w, f.y, acc[11]);
    f = h2_unpack(qb.z); acc[12] = fmaf(w, f.x, acc[12]); acc[13] = fmaf(w, f.y, acc[13]);
    f = h2_unpack(qb.w); acc[14] = fmaf(w, f.x, acc[14]); acc[15] = fmaf(w, f.y, acc[15]);
}

// ---------------------------------------------------------------------------
// Prep: pack W into per-lane mma fragments, split bf16 hi + residual lo.
// ---------------------------------------------------------------------------
__global__ void wfrag_prep(const float* __restrict__ W) {
    int idx = blockIdx.x * blockDim.x + threadIdx.x;   // 0..4095
    if (idx >= 8 * 16 * 32) return;
    int lane = idx & 31;
    int nt   = (idx >> 5) & 15;
    int kc   = idx >> 9;
    int g = lane >> 2, t = lane & 3;
    int nn = nt * 8 + g;
    int k0 = kc * 16 + t * 2;
    float w00 = W[(size_t)k0 * FD + nn];
    float w01 = W[(size_t)(k0 + 1) * FD + nn];
    float w10 = W[(size_t)(k0 + 8) * FD + nn];
    float w11 = W[(size_t)(k0 + 9) * FD + nn];
    float2 f0, f1;
    unsigned h0 = bf2_hi(w00, w01, f0);
    unsigned h1 = bf2_hi(w10, w11, f1);
    g_wbhi[idx] = make_uint2(h0, h1);
    g_wblo[idx] = make_uint2(bf2_pack(w00 - f0.x, w01 - f0.y),
                             bf2_pack(w10 - f1.x, w11 - f1.y));
}

// ---------------------------------------------------------------------------
// Tensor-core GEMM (R16-proven): mma.sync bf16 split precision, N-split
// grid.y=2 -> 32 acc regs, 3 blocks/SM.
// ---------------------------------------------------------------------------
__global__ __launch_bounds__(256) void gemm_mma(
        const float* __restrict__ x,
        const float* __restrict__ att_src,
        const float* __restrict__ att_dst,
        int n) {
    __shared__ unsigned sXhi[TMR * SXW];   // bf16x2 pairs, [row][k2]
    __shared__ unsigned sXlo[TMR * SXW];
    __shared__ float s_att[256];

    const int tid  = threadIdx.x;
    const int w    = tid >> 5;
    const int lane = tid & 31;
    const int g = lane >> 2, t = lane & 3;
    const int row0 = blockIdx.x * TMR;
    const int colB = blockIdx.y;           // 0 or 1

    {
        const float4* x4 = (const float4*)x;
#pragma unroll
        for (int i = 0; i < 16; i++) {
            int idx = tid + 256 * i;              // 0..4095
            int r  = idx >> 5;
            int c4 = idx & 31;
            float4 v = make_float4(0.f, 0.f, 0.f, 0.f);
            if (row0 + r < n) v = x4[(size_t)(row0 + r) * 32 + c4];
            float2 f01, f23;
            unsigned h01 = bf2_hi(v.x, v.y, f01);
            unsigned h23 = bf2_hi(v.z, v.w, f23);
            *(uint2*)&sXhi[r * SXW + c4 * 2] = make_uint2(h01, h23);
            *(uint2*)&sXlo[r * SXW + c4 * 2] =
                make_uint2(bf2_pack(v.x - f01.x, v.y - f01.y),
                           bf2_pack(v.z - f23.x, v.w - f23.y));
        }
        s_att[tid] = (tid < 128) ? att_src[tid] : att_dst[tid - 128];
    }
    __syncthreads();

    float acc[NTB][4];
#pragma unroll
    for (int nt = 0; nt < NTB; nt++)
#pragma unroll
        for (int j = 0; j < 4; j++) acc[nt][j] = 0.f;

    const int wr = w * 16;
    const int rA = (wr + g) * SXW;
    const int rB = (wr + g + 8) * SXW;
#pragma unroll
    for (int kc = 0; kc < 8; kc++) {
        const int p0 = kc * 8 + t;
        const int p1 = p0 + 4;
        unsigned ahi[4], alo[4];
        ahi[0] = sXhi[rA + p0]; ahi[1] = sXhi[rB + p0];
        ahi[2] = sXhi[rA + p1]; ahi[3] = sXhi[rB + p1];
        alo[0] = sXlo[rA + p0]; alo[1] = sXlo[rB + p0];
        alo[2] = sXlo[rA + p1]; alo[3] = sXlo[rB + p1];

        const uint2* __restrict__ bh = &g_wbhi[kc * 512 + (colB * NTB) * 32 + lane];
        const uint2* __restrict__ bl = &g_wblo[kc * 512 + (colB * NTB) * 32 + lane];
#pragma unroll
        for (int nt = 0; nt < NTB; nt++) {
            uint2 bhv = bh[nt * 32];
            uint2 blv = bl[nt * 32];
            mma16816(acc[nt], ahi, bhv);
            mma16816(acc[nt], alo, bhv);
            mma16816(acc[nt], ahi, blv);
        }
    }

    // Epilogue: rows r0 = row0+wr+g, r1 = r0+8; lane covers global cols
    // colB*64 + nt*8 + 2t, +1 -> fp16x2 word index (colB*8+nt)*4 + t.
    const int r0 = row0 + wr + g;
    const int r1 = r0 + 8;
    const bool ok0 = r0 < n, ok1 = r1 < n;

    float vs0[4], vd0[4], vs1[4], vd1[4];
#pragma unroll
    for (int i = 0; i < 4; i++) { vs0[i] = vd0[i] = vs1[i] = vd1[i] = 0.f; }

#pragma unroll
    for (int nt = 0; nt < NTB; nt++) {
        int c = colB * 64 + nt * 8 + t * 2;       // global col
        int wi = (colB * NTB + nt) * 4 + t;       // fp16x2 word index
        int hh = nt >> 1;                         // local head 0..3
        if (ok0) g_xph[(size_t)r0 * 64 + wi] = h2_pack(acc[nt][0], acc[nt][1]);
        if (ok1) g_xph[(size_t)r1 * 64 + wi] = h2_pack(acc[nt][2], acc[nt][3]);
        float as0 = s_att[c], as1 = s_att[c + 1];
        float ad0 = s_att[128 + c], ad1 = s_att[128 + c + 1];
        vs0[hh] += acc[nt][0] * as0 + acc[nt][1] * as1;
        vd0[hh] += acc[nt][0] * ad0 + acc[nt][1] * ad1;
        vs1[hh] += acc[nt][2] * as0 + acc[nt][3] * as1;
        vd1[hh] += acc[nt][2] * ad0 + acc[nt][3] * ad1;
    }
#pragma unroll
    for (int i = 0; i < 4; i++) {
        vs0[i] += __shfl_xor_sync(0xffffffffu, vs0[i], 1);
        vs0[i] += __shfl_xor_sync(0xffffffffu, vs0[i], 2);
        vd0[i] += __shfl_xor_sync(0xffffffffu, vd0[i], 1);
        vd0[i] += __shfl_xor_sync(0xffffffffu, vd0[i], 2);
        vs1[i] += __shfl_xor_sync(0xffffffffu, vs1[i], 1);
        vs1[i] += __shfl_xor_sync(0xffffffffu, vs1[i], 2);
        vd1[i] += __shfl_xor_sync(0xffffffffu, vd1[i], 1);
        vd1[i] += __shfl_xor_sync(0xffffffffu, vd1[i], 2);
    }
    if (t == 0) {
        const int h0 = colB * 4;                  // this block's first head
        if (ok0) {
#pragma unroll
            for (int i = 0; i < 4; i++) {
                g_asrc[(size_t)r0 * HH + h0 + i] = vs0[i];
                g_adst[(size_t)r0 * HH + h0 + i] = vd0[i];
            }
        }
        if (ok1) {
#pragma unroll
            for (int i = 0; i < 4; i++) {
                g_asrc[(size_t)r1 * HH + h0 + i] = vs1[i];
                g_adst[(size_t)r1 * HH + h0 + i] = vd1[i];
            }
        }
    }
}

// ---------------------------------------------------------------------------
// CSR build
// ---------------------------------------------------------------------------
__global__ void zerocnt_kernel(int n) {
    int i = blockIdx.x * blockDim.x + threadIdx.x;
    if (i <= n) g_cnt[i] = 0;
}

__global__ void hist_kernel(const int* __restrict__ ei, int E) {
    int t = blockIdx.x * blockDim.x + threadIdx.x;
    int e = t * 4;
    if (e + 3 < E) {
        int4 d = *(const int4*)&ei[E + e];
        atomicAdd(&g_cnt[d.x], 1);
        atomicAdd(&g_cnt[d.y], 1);
        atomicAdd(&g_cnt[d.z], 1);
        atomicAdd(&g_cnt[d.w], 1);
    } else {
        for (int k = e; k < E && k < e + 4; k++)
            atomicAdd(&g_cnt[ei[E + k]], 1);
    }
}

__global__ void scan1_kernel(int n) {
    const int i = blockIdx.x * SB + threadIdx.x;
    const int lane = threadIdx.x & 31, wid = threadIdx.x >> 5;
    int v = (i < n) ? g_cnt[i] : 0;
    int x = v;
#pragma unroll
    for (int off = 1; off < 32; off <<= 1) {
        int y = __shfl_up_sync(0xffffffffu, x, off);
        if (lane >= off) x += y;
    }
    __shared__ int ws[32];
    if (lane == 31) ws[wid] = x;
    __syncthreads();
    if (wid == 0) {
        int s = ws[lane];
#pragma unroll
        for (int off = 1; off < 32; off <<= 1) {
            int y = __shfl_up_sync(0xffffffffu, s, off);
            if (lane >= off) s += y;
        }
        ws[lane] = s;
    }
    __syncthreads();
    int excl = x - v + (wid ? ws[wid - 1] : 0);
    if (i <= n) g_rowstart[i] = excl;
    if (threadIdx.x == SB - 1) g_bsum[blockIdx.x] = excl + v;
}

__global__ void scan2_kernel(int nb) {
    const int lane = threadIdx.x;
    int v0 = (lane < nb) ? g_bsum[lane] : 0;
    int v1 = (lane + 32 < nb) ? g_bsum[lane + 32] : 0;
    int x0 = v0;
#pragma unroll
    for (int off = 1; off < 32; off <<= 1) {
        int y = __shfl_up_sync(0xffffffffu, x0, off);
        if (lane >= off) x0 += y;
    }
    int tot0 = __shfl_sync(0xffffffffu, x0, 31);
    int x1 = v1;
#pragma unroll
    for (int off = 1; off < 32; off <<= 1) {
        int y = __shfl_up_sync(0xffffffffu, x1, off);
        if (lane >= off) x1 += y;
    }
    if (lane < nb)      g_bsum[lane]      = x0 - v0;
    if (lane + 32 < nb) g_bsum[lane + 32] = tot0 + x1 - v1;
}

__global__ void scan3_kernel(int n) {
    int i = blockIdx.x * SB + threadIdx.x;
    if (i <= n) {
        int v = g_rowstart[i] + g_bsum[blockIdx.x];
        g_rowstart[i] = v;
        if (i < n) g_cursor[i] = v;
    }
}

__global__ void scatter_kernel(const int* __restrict__ ei, int E) {
    int t = blockIdx.x * blockDim.x + threadIdx.x;
    int e = t * 4;
    if (e + 3 < E) {
        int4 s = *(const int4*)&ei[e];
        int4 d = *(const int4*)&ei[E + e];
        int p0 = atomicAdd(&g_cursor[d.x], 1);
        int p1 = atomicAdd(&g_cursor[d.y], 1);
        int p2 = atomicAdd(&g_cursor[d.z], 1);
        int p3 = atomicAdd(&g_cursor[d.w], 1);
        g_csr[p0] = s.x;
        g_csr[p1] = s.y;
        g_csr[p2] = s.z;
        g_csr[p3] = s.w;
    } else {
        for (int k = e; k < E && k < e + 4; k++) {
            int d = ei[E + k];
            int p = atomicAdd(&g_cursor[d], 1);
            g_csr[p] = ei[k];
        }
    }
}

// ---------------------------------------------------------------------------
// Fused aggregate + softmax-normalize + bias + LayerNorm.
// 8 lanes per node (4 nodes/warp): lane l owns head l's 16 features
// (2x LDG.128, 256B/row coalesced) and computes ONE exp per edge —
// 4x fewer MUFU ops than the lane-per-4-features layout.
// ---------------------------------------------------------------------------
__global__ void agg_kernel(const float* __restrict__ bias,
                           const float* __restrict__ gamma,
                           const float* __restrict__ beta,
                           float* __restrict__ out, int n) {
    const int gt = blockIdx.x * blockDim.x + threadIdx.x;
    const int node = gt >> 3;
    if (node >= n) return;
    const int l8 = threadIdx.x & 7;       // head index

    const int row = g_rowstart[node];
    const int end = g_rowstart[node + 1];
    const float adh = g_adst[(size_t)node * HH + l8];
    const uint4* __restrict__ xph4 = (const uint4*)g_xph;   // row stride 16
    const int fo = l8 * 2;                // uint4 offset of this head's chunk

    float acc[16];
#pragma unroll
    for (int j = 0; j < 16; j++) acc[j] = 0.f;
    float wsum = 0.f;

    int i = row;
    for (; i + 1 < end; i += 2) {
        int s0 = g_csr[i];
        int s1 = g_csr[i + 1];
        float a0 = g_asrc[(size_t)s0 * HH + l8];
        float a1 = g_asrc[(size_t)s1 * HH + l8];
        uint4 q00 = xph4[(size_t)s0 * 16 + fo];
        uint4 q01 = xph4[(size_t)s0 * 16 + fo + 1];
        uint4 q10 = xph4[(size_t)s1 * 16 + fo];
        uint4 q11 = xph4[(size_t)s1 * 16 + fo + 1];
        float v0 = a0 + adh; v0 = v0 > 0.f ? v0 : 0.2f * v0;
        float v1 = a1 + adh; v1 = v1 > 0.f ? v1 : 0.2f * v1;
        float w0 = __expf(v0);
        float w1 = __expf(v1);
        accum16(acc, q00, q01, w0);
        accum16(acc, q10, q11, w1);
        wsum += w0 + w1;
    }
    if (i < end) {
        int s = g_csr[i];
        float v = g_asrc[(size_t)s * HH + l8] + adh;
        v = v > 0.f ? v : 0.2f * v;
        float wgt = __expf(v);
        accum16(acc, xph4[(size_t)s * 16 + fo], xph4[(size_t)s * 16 + fo + 1], wgt);
        wsum += wgt;
    }
    // self loop
    {
        float v = g_asrc[(size_t)node * HH + l8] + adh;
        v = v > 0.f ? v : 0.2f * v;
        float wgt = __expf(v);
        accum16(acc, xph4[(size_t)node * 16 + fo], xph4[(size_t)node * 16 + fo + 1], wgt);
        wsum += wgt;
    }

    const float inv_w = 1.f / wsum;
    const int c0 = l8 * 16;
    float o[16];
#pragma unroll
    for (int k = 0; k < 4; k++) {
        float4 b4 = ((const float4*)bias)[l8 * 4 + k];
        o[k*4+0] = acc[k*4+0] * inv_w + b4.x;
        o[k*4+1] = acc[k*4+1] * inv_w + b4.y;
        o[k*4+2] = acc[k*4+2] * inv_w + b4.z;
        o[k*4+3] = acc[k*4+3] * inv_w + b4.w;
    }

    float s1 = 0.f, s2 = 0.f;
#pragma unroll
    for (int j = 0; j < 16; j++) { s1 += o[j]; s2 += o[j] * o[j]; }
#pragma unroll
    for (int off = 4; off; off >>= 1) {   // reduce over the 8-lane node group
        s1 += __shfl_xor_sync(0xffffffffu, s1, off);
        s2 += __shfl_xor_sync(0xffffffffu, s2, off);
    }
    float mu  = s1 * (1.f / 128.f);
    float var = s2 * (1.f / 128.f) - mu * mu;
    float inv = rsqrtf(var + 1e-5f);

#pragma unroll
    for (int k = 0; k < 4; k++) {
        float4 g4 = ((const float4*)gamma)[l8 * 4 + k];
        float4 e4 = ((const float4*)beta)[l8 * 4 + k];
        float4 r;
        r.x = (o[k*4+0] - mu) * inv * g4.x + e4.x;
        r.y = (o[k*4+1] - mu) * inv * g4.y + e4.y;
        r.z = (o[k*4+2] - mu) * inv * g4.z + e4.z;
        r.w = (o[k*4+3] - mu) * inv * g4.w + e4.w;
        ((float4*)out)[(size_t)node * 32 + l8 * 4 + k] = r;
    }
}

// ---------------------------------------------------------------------------
extern "C" void kernel_launch(void* const* d_in, const int* in_sizes, int n_in,
                              void* d_out, int out_size) {
    const float* x       = (const float*)d_in[0];
    const int*   ei      = (const int*)d_in[1];
    const float* W       = (const float*)d_in[2];
    const float* att_src = (const float*)d_in[3];
    const float* att_dst = (const float*)d_in[4];
    const float* bias    = (const float*)d_in[5];
    const float* gamma   = (const float*)d_in[6];
    const float* beta    = (const float*)d_in[7];
    float* out = (float*)d_out;

    const int n = in_sizes[0] / FD;   // 50000
    const int E = in_sizes[1] / 2;    // 800000
    const int nb = (n + 1 + SB - 1) / SB;

    wfrag_prep<<<16, 256>>>(W);                                       // 0
    zerocnt_kernel<<<(n + 1 + 255) / 256, 256>>>(n);                  // 1
    hist_kernel<<<((E + 3) / 4 + 255) / 256, 256>>>(ei, E);           // 2
    dim3 ggrid((n + TMR - 1) / TMR, 2);
    gemm_mma<<<ggrid, 256>>>(x, att_src, att_dst, n);                 // 3 (profiler slot)
    scan1_kernel<<<nb, SB>>>(n);                                      // 4
    scan2_kernel<<<1, 32>>>(nb);                                      // 5
    scan3_kernel<<<nb, SB>>>(n);                                      // 6
    scatter_kernel<<<((E + 3) / 4 + 255) / 256, 256>>>(ei, E);        // 7
    agg_kernel<<<(n * 8 + 255) / 256, 256>>>(bias, gamma, beta, out, n); // 8
}